// round 6
// baseline (speedup 1.0000x reference)
#include <cuda_runtime.h>
#include <cuda_bf16.h>

// Problem constants
#define BB    2
#define SS    2048
#define DD    1024
#define HH    16
#define DHh   64
#define FFD   4096
#define BSR   (BB*SS)          // 4096 rows
#define QC    256              // query-chunk rows per attention pass
#define NCHUNK (SS/QC)         // 8

// ---------------- static scratch (no allocation allowed; keep TOTAL small) ----
__device__ float g_Q  [BB*SS*DD];          // 16 MB
__device__ float g_K  [BB*SS*DD];          // 16 MB
__device__ float g_V  [BB*SS*DD];          // 16 MB
__device__ float g_Sc [BB*HH*QC*SS];       // 64 MB  (score chunk: [b,h,qc,S])
__device__ float g_ctx[BB*SS*DD];          // 16 MB
__device__ float g_ar [BB*SS*DD];          // 16 MB
__device__ float g_y  [BB*SS*DD];          // 16 MB
__device__ float g_h  [BB*SS*FFD];         // 64 MB
__device__ float g_z  [BB*SS*DD];          // 16 MB   -> ~240 MB total

// ---------------- generic tiled fp32 GEMM, register-staged double buffering ----
// C[M,N] = epilogue( alpha * A[M,K] * op(B) )
// BT=true : B is [N,K] row-major (NT gemm, i.e. A @ B^T)
// BT=false: B is [K,N] row-major (NN gemm)
// Batch via blockIdx.z: offset = (z/zdiv)*so? + (z%zdiv)*si?
template<int BM,int BN,int BK,int MG,int NG,bool BT,bool RELU,bool BIAS,bool RES>
__global__ __launch_bounds__(256,2)
void gemm_k(const float* __restrict__ A, int lda,
            const float* __restrict__ Bm, int ldb,
            float*       __restrict__ C,  int ldc,
            int K, float alpha,
            const float* __restrict__ bias,
            const float* __restrict__ res,
            int zdiv,
            long soA, long siA, long soB, long siB, long soC, long siC)
{
    constexpr int ASTR = BM + 4;   // pad keeps 16B alignment, halves transpose STS conflicts
    constexpr int BSTR = BN + 4;
    __shared__ float As[BK][ASTR];
    __shared__ float Bs[BK][BSTR];

    constexpr int KV = BK/4;
    constexpr int NA = (BM*KV)/256;                        // float4 per thread for A tile
    constexpr int NB = BT ? (BN*KV)/256 : (BK*(BN/4))/256; // float4 per thread for B tile

    const int z  = blockIdx.z;
    const long zo = z / zdiv, zi = z % zdiv;
    A  += zo*soA + zi*siA;
    Bm += zo*soB + zi*siB;
    C  += zo*soC + zi*siC;

    const int tid = threadIdx.x;
    const int tr  = tid >> 4;       // 0..15
    const int tc  = tid & 15;       // 0..15
    const int rowBase = blockIdx.y * BM;
    const int colBase = blockIdx.x * BN;

    // precompute per-thread tile-load coordinates
    int aR[NA], aK[NA];
    #pragma unroll
    for (int j = 0; j < NA; j++) {
        int i = tid + j*256;
        aR[j] = i / KV;
        aK[j] = (i % KV) * 4;
    }
    int bR[NB], bK[NB];     // BT: (n-row, k-col)   NN: (k-row, n-col)
    #pragma unroll
    for (int j = 0; j < NB; j++) {
        int i = tid + j*256;
        if (BT) { bR[j] = i / KV;       bK[j] = (i % KV) * 4; }
        else    { bR[j] = i / (BN/4);   bK[j] = (i % (BN/4)) * 4; }
    }

    float acc[MG*4][NG*4];
    #pragma unroll
    for (int i = 0; i < MG*4; i++)
        #pragma unroll
        for (int j = 0; j < NG*4; j++) acc[i][j] = 0.f;

    float4 ra[NA], rb[NB];

    // ---- prologue: fetch tile 0 ----
    #pragma unroll
    for (int j = 0; j < NA; j++)
        ra[j] = *(const float4*)(A + (long)(rowBase + aR[j])*lda + aK[j]);
    #pragma unroll
    for (int j = 0; j < NB; j++)
        rb[j] = BT ? *(const float4*)(Bm + (long)(colBase + bR[j])*ldb + bK[j])
                   : *(const float4*)(Bm + (long)(bR[j])*ldb + (colBase + bK[j]));
    #pragma unroll
    for (int j = 0; j < NA; j++) {
        As[aK[j]+0][aR[j]] = ra[j].x; As[aK[j]+1][aR[j]] = ra[j].y;
        As[aK[j]+2][aR[j]] = ra[j].z; As[aK[j]+3][aR[j]] = ra[j].w;
    }
    #pragma unroll
    for (int j = 0; j < NB; j++) {
        if (BT) {
            Bs[bK[j]+0][bR[j]] = rb[j].x; Bs[bK[j]+1][bR[j]] = rb[j].y;
            Bs[bK[j]+2][bR[j]] = rb[j].z; Bs[bK[j]+3][bR[j]] = rb[j].w;
        } else {
            *(float4*)&Bs[bR[j]][bK[j]] = rb[j];
        }
    }
    __syncthreads();

    for (int k0 = 0; k0 < K; k0 += BK) {
        const bool has_next = (k0 + BK) < K;
        // ---- prefetch next tile into registers (overlaps with compute) ----
        if (has_next) {
            const int kn = k0 + BK;
            #pragma unroll
            for (int j = 0; j < NA; j++)
                ra[j] = *(const float4*)(A + (long)(rowBase + aR[j])*lda + (kn + aK[j]));
            #pragma unroll
            for (int j = 0; j < NB; j++)
                rb[j] = BT ? *(const float4*)(Bm + (long)(colBase + bR[j])*ldb + (kn + bK[j]))
                           : *(const float4*)(Bm + (long)(kn + bR[j])*ldb + (colBase + bK[j]));
        }

        // ---- compute on current smem tile ----
        #pragma unroll
        for (int kk = 0; kk < BK; kk++) {
            float a[MG*4], b[NG*4];
            #pragma unroll
            for (int g = 0; g < MG; g++) {
                float4 v = *(const float4*)&As[kk][g*(BM/MG) + tr*4];
                a[g*4+0]=v.x; a[g*4+1]=v.y; a[g*4+2]=v.z; a[g*4+3]=v.w;
            }
            #pragma unroll
            for (int h = 0; h < NG; h++) {
                float4 v = *(const float4*)&Bs[kk][h*(BN/NG) + tc*4];
                b[h*4+0]=v.x; b[h*4+1]=v.y; b[h*4+2]=v.z; b[h*4+3]=v.w;
            }
            #pragma unroll
            for (int i = 0; i < MG*4; i++)
                #pragma unroll
                for (int j = 0; j < NG*4; j++)
                    acc[i][j] = fmaf(a[i], b[j], acc[i][j]);
        }
        __syncthreads();

        // ---- commit prefetched tile to smem ----
        if (has_next) {
            #pragma unroll
            for (int j = 0; j < NA; j++) {
                As[aK[j]+0][aR[j]] = ra[j].x; As[aK[j]+1][aR[j]] = ra[j].y;
                As[aK[j]+2][aR[j]] = ra[j].z; As[aK[j]+3][aR[j]] = ra[j].w;
            }
            #pragma unroll
            for (int j = 0; j < NB; j++) {
                if (BT) {
                    Bs[bK[j]+0][bR[j]] = rb[j].x; Bs[bK[j]+1][bR[j]] = rb[j].y;
                    Bs[bK[j]+2][bR[j]] = rb[j].z; Bs[bK[j]+3][bR[j]] = rb[j].w;
                } else {
                    *(float4*)&Bs[bR[j]][bK[j]] = rb[j];
                }
            }
            __syncthreads();
        }
    }

    // ---- epilogue ----
    #pragma unroll
    for (int g = 0; g < MG; g++) {
        #pragma unroll
        for (int i = 0; i < 4; i++) {
            long row = rowBase + g*(BM/MG) + tr*4 + i;
            #pragma unroll
            for (int h = 0; h < NG; h++) {
                int col = colBase + h*(BN/NG) + tc*4;
                float4 o;
                o.x = acc[g*4+i][h*4+0] * alpha;
                o.y = acc[g*4+i][h*4+1] * alpha;
                o.z = acc[g*4+i][h*4+2] * alpha;
                o.w = acc[g*4+i][h*4+3] * alpha;
                if (BIAS) {
                    float4 bv = *(const float4*)(bias + col);
                    o.x += bv.x; o.y += bv.y; o.z += bv.z; o.w += bv.w;
                }
                if (RES) {
                    float4 rv = *(const float4*)(res + row*(long)ldc + col);
                    o.x += rv.x; o.y += rv.y; o.z += rv.z; o.w += rv.w;
                }
                if (RELU) {
                    o.x = fmaxf(o.x, 0.f); o.y = fmaxf(o.y, 0.f);
                    o.z = fmaxf(o.z, 0.f); o.w = fmaxf(o.w, 0.f);
                }
                *(float4*)(C + row*(long)ldc + col) = o;
            }
        }
    }
}

// ---------------- softmax over rows of length 2048 (input already relu'd) ----------------
__global__ void softmax_k(float* __restrict__ Sc)
{
    const long row = blockIdx.x;
    float* p = Sc + row * (long)SS;
    const int tid = threadIdx.x;            // 256 threads, 8 elems each
    float4 v0 = ((const float4*)p)[tid];
    float4 v1 = ((const float4*)p)[tid + 256];

    float m = fmaxf(fmaxf(fmaxf(v0.x,v0.y), fmaxf(v0.z,v0.w)),
                    fmaxf(fmaxf(v1.x,v1.y), fmaxf(v1.z,v1.w)));
    #pragma unroll
    for (int o = 16; o; o >>= 1) m = fmaxf(m, __shfl_xor_sync(0xffffffffu, m, o));

    __shared__ float smax[8], ssum[8];
    const int wid = tid >> 5, lid = tid & 31;
    if (lid == 0) smax[wid] = m;
    __syncthreads();
    m = smax[0];
    #pragma unroll
    for (int i = 1; i < 8; i++) m = fmaxf(m, smax[i]);

    float e[8];
    e[0]=__expf(v0.x-m); e[1]=__expf(v0.y-m); e[2]=__expf(v0.z-m); e[3]=__expf(v0.w-m);
    e[4]=__expf(v1.x-m); e[5]=__expf(v1.y-m); e[6]=__expf(v1.z-m); e[7]=__expf(v1.w-m);
    float s = ((e[0]+e[1])+(e[2]+e[3])) + ((e[4]+e[5])+(e[6]+e[7]));
    #pragma unroll
    for (int o = 16; o; o >>= 1) s += __shfl_xor_sync(0xffffffffu, s, o);
    if (lid == 0) ssum[wid] = s;
    __syncthreads();
    s = ssum[0];
    #pragma unroll
    for (int i = 1; i < 8; i++) s += ssum[i];

    const float inv = 1.0f / s;
    float4 o0 = make_float4(e[0]*inv, e[1]*inv, e[2]*inv, e[3]*inv);
    float4 o1 = make_float4(e[4]*inv, e[5]*inv, e[6]*inv, e[7]*inv);
    ((float4*)p)[tid]       = o0;
    ((float4*)p)[tid + 256] = o1;
}

// ---------------- layernorm over rows of length 1024 ----------------
__global__ void ln_k(const float* __restrict__ in, float* __restrict__ out,
                     const float* __restrict__ gw, const float* __restrict__ bw)
{
    const long row = blockIdx.x;
    const float* p = in + row * (long)DD;
    const int tid = threadIdx.x;            // 256 threads, 4 elems each
    float4 v = ((const float4*)p)[tid];
    float s = v.x + v.y + v.z + v.w;
    float q = v.x*v.x + v.y*v.y + v.z*v.z + v.w*v.w;
    #pragma unroll
    for (int o = 16; o; o >>= 1) {
        s += __shfl_xor_sync(0xffffffffu, s, o);
        q += __shfl_xor_sync(0xffffffffu, q, o);
    }
    __shared__ float ss[8], qq[8];
    const int wid = tid >> 5, lid = tid & 31;
    if (lid == 0) { ss[wid] = s; qq[wid] = q; }
    __syncthreads();
    float S = 0.f, Q = 0.f;
    #pragma unroll
    for (int i = 0; i < 8; i++) { S += ss[i]; Q += qq[i]; }

    const float mean = S * (1.0f / DD);
    const float var  = Q * (1.0f / DD) - mean * mean;
    const float inv  = rsqrtf(var + 1e-5f);

    float4 g4 = ((const float4*)gw)[tid];
    float4 b4 = ((const float4*)bw)[tid];
    float4 o;
    o.x = (v.x - mean) * inv * g4.x + b4.x;
    o.y = (v.y - mean) * inv * g4.y + b4.y;
    o.z = (v.z - mean) * inv * g4.z + b4.z;
    o.w = (v.w - mean) * inv * g4.w + b4.w;
    ((float4*)(out + row * (long)DD))[tid] = o;
}

// ---------------- launch ----------------
extern "C" void kernel_launch(void* const* d_in, const int* in_sizes, int n_in,
                              void* d_out, int out_size)
{
    const float* X   = (const float*)d_in[0];
    const float* Wq  = (const float*)d_in[1];
    const float* Wk  = (const float*)d_in[2];
    const float* Wo  = (const float*)d_in[3];
    const float* l1g = (const float*)d_in[4];
    const float* l1b = (const float*)d_in[5];
    const float* l2g = (const float*)d_in[6];
    const float* l2b = (const float*)d_in[7];
    const float* W1  = (const float*)d_in[8];
    const float* b1  = (const float*)d_in[9];
    const float* W2  = (const float*)d_in[10];
    const float* b2  = (const float*)d_in[11];
    float* out = (float*)d_out;

    float *Q, *K, *V, *Sc, *CT, *AR, *Y, *Hh, *Z;
    cudaGetSymbolAddress((void**)&Q,  g_Q);
    cudaGetSymbolAddress((void**)&K,  g_K);
    cudaGetSymbolAddress((void**)&V,  g_V);
    cudaGetSymbolAddress((void**)&Sc, g_Sc);
    cudaGetSymbolAddress((void**)&CT, g_ctx);
    cudaGetSymbolAddress((void**)&AR, g_ar);
    cudaGetSymbolAddress((void**)&Y,  g_y);
    cudaGetSymbolAddress((void**)&Hh, g_h);
    cudaGetSymbolAddress((void**)&Z,  g_z);

    const dim3 blk(256);
    const dim3 gproj(DD/128,  BSR/128, 1);    // M=4096, N=1024
    const dim3 gscC (SS/128,  QC/128,  BB*HH);// scores for one query chunk
    const dim3 gctxC(DHh/64,  QC/128,  BB*HH);// ctx for one query chunk
    const dim3 gf1  (FFD/128, BSR/128, 1);    // M=4096, N=4096

    // --- QKV projections: Q/K = X@Wq^T / X@Wk^T, V = X@Wo^T ---
    gemm_k<128,128,16,2,2,true,false,false,false><<<gproj, blk>>>(
        X, DD, Wq, DD, Q, DD, DD, 1.f, nullptr, nullptr, 1, 0,0,0,0,0,0);
    gemm_k<128,128,16,2,2,true,false,false,false><<<gproj, blk>>>(
        X, DD, Wk, DD, K, DD, DD, 1.f, nullptr, nullptr, 1, 0,0,0,0,0,0);
    gemm_k<128,128,16,2,2,true,false,false,false><<<gproj, blk>>>(
        X, DD, Wo, DD, V, DD, DD, 1.f, nullptr, nullptr, 1, 0,0,0,0,0,0);

    // --- attention, chunked over query rows to keep the score buffer small ---
    for (int c = 0; c < NCHUNK; c++) {
        // scores chunk: relu(Q[c] @ K^T / 8), batched over (b,h)
        gemm_k<128,128,16,2,2,true,true,false,false><<<gscC, blk>>>(
            Q + (long)c*QC*DD, DD, K, DD, Sc, SS, DHh, 0.125f, nullptr, nullptr,
            HH, (long)SS*DD, (long)DHh,
                (long)SS*DD, (long)DHh,
                (long)HH*QC*SS, (long)QC*SS);

        // softmax over keys for this chunk
        softmax_k<<<BB*HH*QC, 256>>>(Sc);

        // ctx chunk = attn[c] @ V_h  (NN gemm, N=64)
        gemm_k<128,64,16,2,1,false,false,false,false><<<gctxC, blk>>>(
            Sc, SS, V, DD, CT + (long)c*QC*DD, DD, SS, 1.f, nullptr, nullptr,
            HH, (long)HH*QC*SS, (long)QC*SS,
                (long)SS*DD, (long)DHh,
                (long)SS*DD, (long)DHh);
    }

    // --- out-proj + residual X ---
    gemm_k<128,128,16,2,2,true,false,false,true><<<gproj, blk>>>(
        CT, DD, Wo, DD, AR, DD, DD, 1.f, nullptr, X, 1, 0,0,0,0,0,0);

    // --- LN1 -> y ---
    ln_k<<<BSR, 256>>>(AR, Y, l1g, l1b);

    // --- FFN1: relu(y @ W1^T + b1) ---
    gemm_k<128,128,16,2,2,true,true,true,false><<<gf1, blk>>>(
        Y, DD, W1, DD, Hh, FFD, DD, 1.f, b1, nullptr, 1, 0,0,0,0,0,0);

    // --- FFN2: h @ W2^T + b2 + y ---
    gemm_k<128,128,16,2,2,true,false,true,true><<<gproj, blk>>>(
        Hh, FFD, W2, FFD, Z, DD, FFD, 1.f, b2, Y, 1, 0,0,0,0,0,0);

    // --- LN2 -> out ---
    ln_k<<<BSR, 256>>>(Z, out, l2g, l2b);
}